// round 3
// baseline (speedup 1.0000x reference)
#include <cuda_runtime.h>

#define B_  8
#define T_  1024
#define H_  8
#define D_  64
#define NF_ 512
#define PL_ 2047

// -------- scratch (static device globals; no allocation) --------
__device__ float g_Q[B_*H_*T_*D_];
__device__ float g_K[B_*H_*T_*D_];
__device__ float g_V[B_*H_*T_*D_];
__device__ float g_P[H_*PL_*D_];
__device__ float g_X[B_*T_*NF_];

// ======================================================================
// SGEMM-NT: C = A[M,512] @ W[512,512]^T + bias, with output remap modes.
// mode 0: C[r*512+c] (plain row-major)
// mode 1: qkv remap  -> [B,H,T,D]
// mode 2: pos remap  -> [H,PL,D]
// ======================================================================
__global__ void __launch_bounds__(256) sgemm_nt(
    const float* __restrict__ A, const float* __restrict__ W,
    const float* __restrict__ bias, float* __restrict__ C,
    int M, int mode)
{
    __shared__ float As[16][68];   // As[k][m]
    __shared__ float Bs[16][68];   // Bs[k][n] = W[n][k]
    const int tid = threadIdx.x;
    const int tx = tid & 15, ty = tid >> 4;
    const int n0 = blockIdx.x * 64;
    const int m0 = blockIdx.y * 64;

    float acc[4][4];
#pragma unroll
    for (int i = 0; i < 4; i++)
#pragma unroll
        for (int j = 0; j < 4; j++) acc[i][j] = 0.f;

    const int lr = tid >> 2;          // 0..63
    const int lc = (tid & 3) * 4;     // k sub-offset

    for (int k0 = 0; k0 < 512; k0 += 16) {
        // load A tile (transposed into As[k][m]) with row guard
        float4 a4 = make_float4(0.f, 0.f, 0.f, 0.f);
        int gr = m0 + lr;
        if (gr < M) a4 = *(const float4*)(A + (size_t)gr * 512 + k0 + lc);
        As[lc + 0][lr] = a4.x; As[lc + 1][lr] = a4.y;
        As[lc + 2][lr] = a4.z; As[lc + 3][lr] = a4.w;
        // load W tile (N=512 always full)
        float4 b4 = *(const float4*)(W + (size_t)(n0 + lr) * 512 + k0 + lc);
        Bs[lc + 0][lr] = b4.x; Bs[lc + 1][lr] = b4.y;
        Bs[lc + 2][lr] = b4.z; Bs[lc + 3][lr] = b4.w;
        __syncthreads();
#pragma unroll
        for (int kk = 0; kk < 16; kk++) {
            float4 av = *(const float4*)&As[kk][ty * 4];
            float4 bv = *(const float4*)&Bs[kk][tx * 4];
            float a_[4] = {av.x, av.y, av.z, av.w};
            float b_[4] = {bv.x, bv.y, bv.z, bv.w};
#pragma unroll
            for (int i = 0; i < 4; i++)
#pragma unroll
                for (int j = 0; j < 4; j++) acc[i][j] += a_[i] * b_[j];
        }
        __syncthreads();
    }

#pragma unroll
    for (int i = 0; i < 4; i++) {
        int r = m0 + ty * 4 + i;
        if (r >= M) continue;
#pragma unroll
        for (int j = 0; j < 4; j++) {
            int c = n0 + tx * 4 + j;
            float v = acc[i][j] + (bias ? bias[c] : 0.f);
            if (mode == 0) {
                C[(size_t)r * 512 + c] = v;
            } else if (mode == 1) {
                int b = r >> 10, t = r & 1023;
                int h = c >> 6,  d = c & 63;
                C[(((size_t)(b * H_ + h)) * T_ + t) * D_ + d] = v;
            } else { // mode 2
                int h = c >> 6, d = c & 63;
                C[((size_t)h * PL_ + r) * D_ + d] = v;
            }
        }
    }
}

// ======================================================================
// Fused rel-pos flash attention.
// grid: (T/64, B*H). block: 256 threads. ~105KB dynamic smem.
// bd[i][l] = qu_i . p_l + wp[l],  wp[l] = (v_bias - u_bias) . p_l
// Ring buffer of 128 l-columns: per j-tile only 64 new columns computed.
// Mask dtype is runtime-sniffed: harness may pass bool as u8 OR widened to
// int32/float32. Word-mode test (w != 0) covers both int32 and float32.
// ======================================================================
__global__ void __launch_bounds__(256, 2) attn_kernel(
    const float* __restrict__ Q, const float* __restrict__ K,
    const float* __restrict__ V, const float* __restrict__ P,
    const unsigned char* __restrict__ mask,
    const float* __restrict__ pbu, const float* __restrict__ pbv,
    float* __restrict__ X)
{
    extern __shared__ float sm[];
    float* quT  = sm;                 // [64 d][68]  quT[d*68 + r]
    float* sT   = quT + 64 * 68;      // p tile pT[d*68+lc]  OR scores sT[j*68+r]
    float* ktT  = sT  + 64 * 68;      // ktT[d*68 + j]
    float* vt   = ktT + 64 * 68;      // vt[j*68 + d]
    float* bd   = vt  + 64 * 68;      // [64 i][128 ring]
    float* wp   = bd  + 64 * 128;     // [64]
    float* duv  = wp  + 64;           // [64]
    float* mrun = duv + 64;
    float* lrun = mrun + 64;
    float* rsc  = lrun + 64;
    unsigned char* mt = (unsigned char*)(rsc + 64); // [64*64] bytes

    __shared__ int s_bytemode;

    const int tid = threadIdx.x;
    const int tx = tid & 15, ty = tid >> 4;
    const int bh = blockIdx.y;
    const int b = bh >> 3, h = bh & 7;
    const int i0 = blockIdx.x * 64;

    // ---- mask dtype sniff: byte-packed bools vs 4-byte (int32/float32) ----
    if (tid == 0) s_bytemode = 0;
    __syncthreads();
    {
        unsigned w = ((const unsigned*)mask)[tid];   // first 1KB of mask
        if (w != 0u && w != 1u && w != 0x3F800000u) atomicOr(&s_bytemode, 1);
    }

    // ---- load Q tile, add pos_bias_u, store transposed ----
    {
        const float* qp = Q + ((size_t)bh * T_ + i0) * D_;
        const float* up = pbu + h * D_;
#pragma unroll
        for (int s = 0; s < 4; s++) {
            int f = tid + 256 * s;
            int r = f >> 4, c4 = (f & 15) * 4;
            float4 v4 = *(const float4*)(qp + r * D_ + c4);
            quT[(c4 + 0) * 68 + r] = v4.x + up[c4 + 0];
            quT[(c4 + 1) * 68 + r] = v4.y + up[c4 + 1];
            quT[(c4 + 2) * 68 + r] = v4.z + up[c4 + 2];
            quT[(c4 + 3) * 68 + r] = v4.w + up[c4 + 3];
        }
    }
    if (tid < 64) {
        duv[tid]  = pbv[h * D_ + tid] - pbu[h * D_ + tid];
        mrun[tid] = -1e30f;
        lrun[tid] = 0.f;
    }

    float o[4][4];
#pragma unroll
    for (int i = 0; i < 4; i++)
#pragma unroll
        for (int j = 0; j < 4; j++) o[i][j] = 0.f;

    const float* Ph = P + (size_t)h * PL_ * D_;

    // jt = -1: prefill first half of bd ring. jt >= 0: full j-tiles.
    for (int jt = -1; jt < 16; jt++) {
        const int j0 = (jt < 0) ? 0 : jt * 64;
        const int Lb = (jt < 0) ? (960 - i0) : (1024 - i0 + j0);
        const int colbase = (jt < 0) ? 0 : ((64 + j0) & 127);

        if (jt >= 0) {
            // load K tile (transposed), V tile (row-major), mask tile
            const float* kp = K + ((size_t)bh * T_ + j0) * D_;
            const float* vp = V + ((size_t)bh * T_ + j0) * D_;
#pragma unroll
            for (int s = 0; s < 4; s++) {
                int f = tid + 256 * s;
                int r = f >> 4, c4 = (f & 15) * 4;
                float4 kv = *(const float4*)(kp + r * D_ + c4);
                ktT[(c4 + 0) * 68 + r] = kv.x;
                ktT[(c4 + 1) * 68 + r] = kv.y;
                ktT[(c4 + 2) * 68 + r] = kv.z;
                ktT[(c4 + 3) * 68 + r] = kv.w;
                float4 vv = *(const float4*)(vp + r * D_ + c4);
                *(float4*)(vt + r * 68 + c4) = vv;
            }
            {
                int r = tid >> 2; int off = (tid & 3) * 16;
                size_t elem = (size_t)(b * T_ + i0 + r) * T_ + j0 + off;
                if (s_bytemode) {
                    *(uint4*)(mt + r * 64 + off) = *(const uint4*)(mask + elem);
                } else {
                    const uint4* mp = (const uint4*)((const unsigned*)mask + elem);
#pragma unroll
                    for (int q4 = 0; q4 < 4; q4++) {
                        uint4 m4 = mp[q4];
                        mt[r * 64 + off + q4 * 4 + 0] = (m4.x != 0u);
                        mt[r * 64 + off + q4 * 4 + 1] = (m4.y != 0u);
                        mt[r * 64 + off + q4 * 4 + 2] = (m4.z != 0u);
                        mt[r * 64 + off + q4 * 4 + 3] = (m4.w != 0u);
                    }
                }
            }
        }
        // load p window rows [Lb, Lb+64) transposed into sT (acting as pT)
#pragma unroll
        for (int s = 0; s < 4; s++) {
            int f = tid + 256 * s;
            int r = f >> 4, c4 = (f & 15) * 4;
            int l = Lb + r;
            float4 pv = make_float4(0.f, 0.f, 0.f, 0.f);
            if (l < PL_) pv = *(const float4*)(Ph + (size_t)l * D_ + c4);
            sT[(c4 + 0) * 68 + r] = pv.x;
            sT[(c4 + 1) * 68 + r] = pv.y;
            sT[(c4 + 2) * 68 + r] = pv.z;
            sT[(c4 + 3) * 68 + r] = pv.w;
        }
        __syncthreads();

        // wp[l] = (v-u) . p_l
        if (tid < 64) {
            float acc = 0.f;
#pragma unroll 16
            for (int d = 0; d < 64; d++) acc += duv[d] * sT[d * 68 + tid];
            wp[tid] = acc;
        }
        __syncthreads();

        // bd gemm: bd[i][ring] = quT . pT + wp
        {
            float acc[4][4];
#pragma unroll
            for (int i = 0; i < 4; i++)
#pragma unroll
                for (int j = 0; j < 4; j++) acc[i][j] = 0.f;
#pragma unroll 8
            for (int d = 0; d < 64; d++) {
                float4 av = *(const float4*)&quT[d * 68 + ty * 4];
                float4 pv = *(const float4*)&sT[d * 68 + tx * 4];
                float a_[4] = {av.x, av.y, av.z, av.w};
                float p_[4] = {pv.x, pv.y, pv.z, pv.w};
#pragma unroll
                for (int i = 0; i < 4; i++)
#pragma unroll
                    for (int j = 0; j < 4; j++) acc[i][j] += a_[i] * p_[j];
            }
#pragma unroll
            for (int i = 0; i < 4; i++)
#pragma unroll
                for (int j = 0; j < 4; j++)
                    bd[(ty * 4 + i) * 128 + colbase + tx * 4 + j] =
                        acc[i][j] + wp[tx * 4 + j];
        }
        __syncthreads();
        if (jt < 0) continue;

        // score gemm: s = (qu . k + bd) * 0.125, masked -> -10000
        {
            float acc[4][4];
#pragma unroll
            for (int i = 0; i < 4; i++)
#pragma unroll
                for (int j = 0; j < 4; j++) acc[i][j] = 0.f;
#pragma unroll 8
            for (int d = 0; d < 64; d++) {
                float4 av = *(const float4*)&quT[d * 68 + ty * 4];
                float4 kv = *(const float4*)&ktT[d * 68 + tx * 4];
                float a_[4] = {av.x, av.y, av.z, av.w};
                float k_[4] = {kv.x, kv.y, kv.z, kv.w};
#pragma unroll
                for (int i = 0; i < 4; i++)
#pragma unroll
                    for (int j = 0; j < 4; j++) acc[i][j] += a_[i] * k_[j];
            }
#pragma unroll
            for (int i = 0; i < 4; i++) {
                int ri = ty * 4 + i;
#pragma unroll
                for (int j = 0; j < 4; j++) {
                    int cj = tx * 4 + j;
                    float bdv = bd[ri * 128 + ((63 - ri + j0 + cj) & 127)];
                    float sc = (acc[i][j] + bdv) * 0.125f;
                    if (mt[ri * 64 + cj]) sc = -10000.f;
                    sT[cj * 68 + ri] = sc;
                }
            }
        }
        __syncthreads();

        // online softmax update (4 threads per row)
        {
            int r = tid >> 2, sg = tid & 3;
            float mloc = -1e30f;
#pragma unroll 16
            for (int c = 0; c < 16; c++)
                mloc = fmaxf(mloc, sT[(sg * 16 + c) * 68 + r]);
            mloc = fmaxf(mloc, __shfl_xor_sync(0xffffffffu, mloc, 1));
            mloc = fmaxf(mloc, __shfl_xor_sync(0xffffffffu, mloc, 2));
            float mold = mrun[r];
            float mnew = fmaxf(mold, mloc);
            float scale = __expf(mold - mnew);
            float ls = 0.f;
#pragma unroll 16
            for (int c = 0; c < 16; c++) {
                int cc = sg * 16 + c;
                float p = __expf(sT[cc * 68 + r] - mnew);
                ls += p;                                  // denominator keeps masked terms (== ref)
                sT[cc * 68 + r] = mt[r * 64 + cc] ? 0.f : p; // numerator zeroed (== ref)
            }
            ls += __shfl_xor_sync(0xffffffffu, ls, 1);
            ls += __shfl_xor_sync(0xffffffffu, ls, 2);
            if (sg == 0) {
                mrun[r] = mnew;
                lrun[r] = lrun[r] * scale + ls;
                rsc[r]  = scale;
            }
        }
        __syncthreads();

        // rescale O and accumulate P @ V
        {
            float s_[4];
#pragma unroll
            for (int i = 0; i < 4; i++) s_[i] = rsc[ty * 4 + i];
#pragma unroll
            for (int i = 0; i < 4; i++)
#pragma unroll
                for (int j = 0; j < 4; j++) o[i][j] *= s_[i];
#pragma unroll 8
            for (int jj = 0; jj < 64; jj++) {
                float4 av = *(const float4*)&sT[jj * 68 + ty * 4];
                float4 vv = *(const float4*)&vt[jj * 68 + tx * 4];
                float a_[4] = {av.x, av.y, av.z, av.w};
                float v_[4] = {vv.x, vv.y, vv.z, vv.w};
#pragma unroll
                for (int i = 0; i < 4; i++)
#pragma unroll
                    for (int j = 0; j < 4; j++) o[i][j] += a_[i] * v_[j];
            }
        }
        __syncthreads();
    }

    // epilogue: normalize and write X[b, t, h*64 + d]
    {
        float* xp = g_X + (size_t)(b * T_ + i0) * NF_ + h * D_;
#pragma unroll
        for (int i = 0; i < 4; i++) {
            int r = ty * 4 + i;
            float inv = 1.f / lrun[r];
            float4 v4 = make_float4(o[i][0] * inv, o[i][1] * inv,
                                    o[i][2] * inv, o[i][3] * inv);
            *(float4*)(xp + (size_t)r * NF_ + tx * 4) = v4;
        }
    }
    (void)X;
}

// ======================================================================
extern "C" void kernel_launch(void* const* d_in, const int* in_sizes, int n_in,
                              void* d_out, int out_size)
{
    const float* query   = (const float*)d_in[0];
    const float* key     = (const float*)d_in[1];
    const float* value   = (const float*)d_in[2];
    const unsigned char* mask = (const unsigned char*)d_in[3];
    const float* pos_emb = (const float*)d_in[4];
    const float* Wq  = (const float*)d_in[5];
    const float* bq  = (const float*)d_in[6];
    const float* Wk  = (const float*)d_in[7];
    const float* bk  = (const float*)d_in[8];
    const float* Wv  = (const float*)d_in[9];
    const float* bv  = (const float*)d_in[10];
    const float* Wpos= (const float*)d_in[11];
    const float* Wo  = (const float*)d_in[12];
    const float* bo  = (const float*)d_in[13];
    const float* pbu = (const float*)d_in[14];
    const float* pbv = (const float*)d_in[15];

    float *Qd, *Kd, *Vd, *Pd, *Xd;
    cudaGetSymbolAddress((void**)&Qd, g_Q);
    cudaGetSymbolAddress((void**)&Kd, g_K);
    cudaGetSymbolAddress((void**)&Vd, g_V);
    cudaGetSymbolAddress((void**)&Pd, g_P);
    cudaGetSymbolAddress((void**)&Xd, g_X);

    const int SMEM = (4 * 64 * 68 + 64 * 128 + 5 * 64) * 4 + 64 * 64; // 107776 B
    cudaFuncSetAttribute(attn_kernel,
                         cudaFuncAttributeMaxDynamicSharedMemorySize, SMEM);

    // projections
    sgemm_nt<<<dim3(8, 128), 256>>>(query,  Wq,  bq,  Qd, B_ * T_, 1);
    sgemm_nt<<<dim3(8, 128), 256>>>(key,    Wk,  bk,  Kd, B_ * T_, 1);
    sgemm_nt<<<dim3(8, 128), 256>>>(value,  Wv,  bv,  Vd, B_ * T_, 1);
    sgemm_nt<<<dim3(8, 32),  256>>>(pos_emb, Wpos, nullptr, Pd, PL_, 2);

    // fused attention
    attn_kernel<<<dim3(T_ / 64, B_ * H_), 256, SMEM>>>(
        Qd, Kd, Vd, Pd, mask, pbu, pbv, Xd);

    // output projection
    sgemm_nt<<<dim3(8, 128), 256>>>(Xd, Wo, bo, (float*)d_out, B_ * T_, 0);
}

// round 7
// speedup vs baseline: 1.3025x; 1.3025x over previous
#include <cuda_runtime.h>
#include <cuda_bf16.h>

#define B_  8
#define T_  1024
#define H_  8
#define D_  64
#define NF_ 512
#define PL_ 2047

// -------- scratch (static device globals; no allocation) --------
__device__ float g_Q[B_*H_*T_*D_];
__device__ float g_K[B_*H_*T_*D_];
__device__ float g_V[B_*H_*T_*D_];
__device__ float g_P[H_*PL_*D_];
__device__ float g_X[B_*T_*NF_];

// ===================== mma.sync helpers (base ISA, sm_80+) =============
__device__ __forceinline__ unsigned smem_u32(const void* p) {
    unsigned a;
    asm("{ .reg .u64 t; cvta.to.shared.u64 t, %1; cvt.u32.u64 %0, t; }"
        : "=r"(a) : "l"(p));
    return a;
}
__device__ __forceinline__ void ldsm_x4(unsigned* r, unsigned addr) {
    asm volatile("ldmatrix.sync.aligned.m8n8.x4.shared.b16 {%0,%1,%2,%3}, [%4];"
                 : "=r"(r[0]), "=r"(r[1]), "=r"(r[2]), "=r"(r[3]) : "r"(addr));
}
__device__ __forceinline__ void ldsm_x2(unsigned* r, unsigned addr) {
    asm volatile("ldmatrix.sync.aligned.m8n8.x2.shared.b16 {%0,%1}, [%2];"
                 : "=r"(r[0]), "=r"(r[1]) : "r"(addr));
}
__device__ __forceinline__ void mma_bf16(float* c, const unsigned* a, const unsigned* b) {
    asm volatile(
        "mma.sync.aligned.m16n8k16.row.col.f32.bf16.bf16.f32 "
        "{%0,%1,%2,%3}, {%4,%5,%6,%7}, {%8,%9}, {%0,%1,%2,%3};"
        : "+f"(c[0]), "+f"(c[1]), "+f"(c[2]), "+f"(c[3])
        : "r"(a[0]), "r"(a[1]), "r"(a[2]), "r"(a[3]), "r"(b[0]), "r"(b[1]));
}
__device__ __forceinline__ void split_bf16(float4 v, uint2& h, uint2& l) {
    __nv_bfloat16 h0 = __float2bfloat16(v.x), h1 = __float2bfloat16(v.y);
    __nv_bfloat16 h2 = __float2bfloat16(v.z), h3 = __float2bfloat16(v.w);
    __nv_bfloat16 l0 = __float2bfloat16(v.x - __bfloat162float(h0));
    __nv_bfloat16 l1 = __float2bfloat16(v.y - __bfloat162float(h1));
    __nv_bfloat16 l2 = __float2bfloat16(v.z - __bfloat162float(h2));
    __nv_bfloat16 l3 = __float2bfloat16(v.w - __bfloat162float(h3));
    h.x = (unsigned)__bfloat16_as_ushort(h0) | ((unsigned)__bfloat16_as_ushort(h1) << 16);
    h.y = (unsigned)__bfloat16_as_ushort(h2) | ((unsigned)__bfloat16_as_ushort(h3) << 16);
    l.x = (unsigned)__bfloat16_as_ushort(l0) | ((unsigned)__bfloat16_as_ushort(l1) << 16);
    l.y = (unsigned)__bfloat16_as_ushort(l2) | ((unsigned)__bfloat16_as_ushort(l3) << 16);
}

// ======================================================================
// bf16x2-split tensor-core SGEMM-NT:  C[M,512] = A[M,512] @ W[512,512]^T + bias
// Tile 128x128, K-chunk 32, double-buffered smem, 8 warps (4m x 2n),
// warp tile 32x64 (2x8 mma.m16n8k16), 3 passes AhBh+AhBl+AlBh -> fp32.
// mode 0: row-major.  mode 1: -> [B,H,T,D].  mode 2: -> [H,PL,D].
// ======================================================================
#define LDA 40                       // bf16 elems per smem row (80B, 16B-mult)
#define MATB (128 * LDA * 2)         // 10240 B per matrix
#define BUFB (4 * MATB)              // Ah, Al, Bh, Bl

__global__ void __launch_bounds__(256) sgemm_mma(
    const float* __restrict__ A, const float* __restrict__ W,
    const float* __restrict__ bias, float* __restrict__ C,
    int M, int mode)
{
    extern __shared__ __align__(16) unsigned char smem[];
    const unsigned sbase = smem_u32(smem);
    const int tid = threadIdx.x;
    const int lane = tid & 31, wid = tid >> 5;
    const int wm = wid & 3, wn = wid >> 2;
    const int m0 = blockIdx.y * 128;
    const int n0 = blockIdx.x * 128;

    float acc[2][8][4];
#pragma unroll
    for (int mi = 0; mi < 2; mi++)
#pragma unroll
        for (int ni = 0; ni < 8; ni++)
#pragma unroll
            for (int q = 0; q < 4; q++) acc[mi][ni][q] = 0.f;

    const int lrow = tid >> 3;            // 0..31
    const int lcol = (tid & 7) * 4;       // 0..28

    // ---- preload chunk 0 ----
    {
#pragma unroll
        for (int i = 0; i < 4; i++) {
            int r = lrow + 32 * i;
            float4 a4 = make_float4(0.f, 0.f, 0.f, 0.f);
            if (m0 + r < M) a4 = *(const float4*)(A + (size_t)(m0 + r) * 512 + lcol);
            float4 b4 = *(const float4*)(W + (size_t)(n0 + r) * 512 + lcol);
            uint2 h, l;
            split_bf16(a4, h, l);
            *(uint2*)(smem + (size_t)r * LDA * 2 + lcol * 2) = h;
            *(uint2*)(smem + MATB + (size_t)r * LDA * 2 + lcol * 2) = l;
            split_bf16(b4, h, l);
            *(uint2*)(smem + 2 * MATB + (size_t)r * LDA * 2 + lcol * 2) = h;
            *(uint2*)(smem + 3 * MATB + (size_t)r * LDA * 2 + lcol * 2) = l;
        }
    }
    __syncthreads();

    // fragment smem offsets (within one matrix)
    const unsigned aoff = ((unsigned)(wm * 32 + (lane & 15)) * LDA + (lane >> 4) * 8) * 2;
    const unsigned boff = ((unsigned)(wn * 64 + (lane & 7)) * LDA + ((lane >> 3) & 1) * 8) * 2;

    for (int c = 0; c < 16; c++) {
        const unsigned buf = sbase + (unsigned)(c & 1) * BUFB;
        const int nb = (c + 1) & 1;

        // ---- issue prefetch LDGs for chunk c+1 (in flight during mma) ----
        float4 pa[4], pb[4];
        if (c < 15) {
            const int k0 = (c + 1) * 32;
#pragma unroll
            for (int i = 0; i < 4; i++) {
                int r = lrow + 32 * i;
                pa[i] = make_float4(0.f, 0.f, 0.f, 0.f);
                if (m0 + r < M)
                    pa[i] = *(const float4*)(A + (size_t)(m0 + r) * 512 + k0 + lcol);
                pb[i] = *(const float4*)(W + (size_t)(n0 + r) * 512 + k0 + lcol);
            }
        }

        // ---- mma on buffer c&1: 2 k16 steps x 3 passes ----
#pragma unroll
        for (int ks = 0; ks < 2; ks++) {
            const unsigned kb = (unsigned)(ks * 16) * 2;
            unsigned ah[2][4], al[2][4], bh[8][2], bl[8][2];
#pragma unroll
            for (int mi = 0; mi < 2; mi++) {
                ldsm_x4(ah[mi], buf + aoff + (unsigned)mi * (16 * LDA * 2) + kb);
                ldsm_x4(al[mi], buf + MATB + aoff + (unsigned)mi * (16 * LDA * 2) + kb);
            }
#pragma unroll
            for (int ni = 0; ni < 8; ni++) {
                ldsm_x2(bh[ni], buf + 2 * MATB + boff + (unsigned)ni * (8 * LDA * 2) + kb);
                ldsm_x2(bl[ni], buf + 3 * MATB + boff + (unsigned)ni * (8 * LDA * 2) + kb);
            }
#pragma unroll
            for (int mi = 0; mi < 2; mi++)
#pragma unroll
                for (int ni = 0; ni < 8; ni++) mma_bf16(acc[mi][ni], ah[mi], bh[ni]);
#pragma unroll
            for (int mi = 0; mi < 2; mi++)
#pragma unroll
                for (int ni = 0; ni < 8; ni++) mma_bf16(acc[mi][ni], ah[mi], bl[ni]);
#pragma unroll
            for (int mi = 0; mi < 2; mi++)
#pragma unroll
                for (int ni = 0; ni < 8; ni++) mma_bf16(acc[mi][ni], al[mi], bh[ni]);
        }

        // ---- convert + store prefetched chunk into the other buffer ----
        if (c < 15) {
            unsigned char* dst = smem + (size_t)nb * BUFB;
#pragma unroll
            for (int i = 0; i < 4; i++) {
                int r = lrow + 32 * i;
                uint2 h, l;
                split_bf16(pa[i], h, l);
                *(uint2*)(dst + (size_t)r * LDA * 2 + lcol * 2) = h;
                *(uint2*)(dst + MATB + (size_t)r * LDA * 2 + lcol * 2) = l;
                split_bf16(pb[i], h, l);
                *(uint2*)(dst + 2 * MATB + (size_t)r * LDA * 2 + lcol * 2) = h;
                *(uint2*)(dst + 3 * MATB + (size_t)r * LDA * 2 + lcol * 2) = l;
            }
        }
        __syncthreads();
    }

    // ---- epilogue: bias + remap, float2 stores ----
    {
        const int tq = lane >> 2, tr = (lane & 3) * 2;
#pragma unroll
        for (int mi = 0; mi < 2; mi++) {
#pragma unroll
            for (int ni = 0; ni < 8; ni++) {
                const int gcol = n0 + wn * 64 + ni * 8 + tr;
                float bx = 0.f, by = 0.f;
                if (bias) { bx = bias[gcol]; by = bias[gcol + 1]; }
#pragma unroll
                for (int hf = 0; hf < 2; hf++) {
                    const int row = m0 + wm * 32 + mi * 16 + tq + hf * 8;
                    if (row >= M) continue;
                    float2 v;
                    v.x = acc[mi][ni][hf * 2 + 0] + bx;
                    v.y = acc[mi][ni][hf * 2 + 1] + by;
                    float* op;
                    if (mode == 0) {
                        op = C + (size_t)row * 512 + gcol;
                    } else if (mode == 1) {
                        int bb = row >> 10, t = row & 1023;
                        int h = gcol >> 6, d0 = gcol & 63;
                        op = C + (((size_t)(bb * H_ + h)) * T_ + t) * D_ + d0;
                    } else {
                        int h = gcol >> 6, d0 = gcol & 63;
                        op = C + ((size_t)h * PL_ + row) * D_ + d0;
                    }
                    *(float2*)op = v;
                }
            }
        }
    }
}

// ======================================================================
// Fused rel-pos flash attention (fp32, unchanged from passing round 3).
// ======================================================================
__global__ void __launch_bounds__(256, 2) attn_kernel(
    const float* __restrict__ Q, const float* __restrict__ K,
    const float* __restrict__ V, const float* __restrict__ P,
    const unsigned char* __restrict__ mask,
    const float* __restrict__ pbu, const float* __restrict__ pbv,
    float* __restrict__ X)
{
    extern __shared__ float sm[];
    float* quT  = sm;
    float* sT   = quT + 64 * 68;
    float* ktT  = sT  + 64 * 68;
    float* vt   = ktT + 64 * 68;
    float* bd   = vt  + 64 * 68;
    float* wp   = bd  + 64 * 128;
    float* duv  = wp  + 64;
    float* mrun = duv + 64;
    float* lrun = mrun + 64;
    float* rsc  = lrun + 64;
    unsigned char* mt = (unsigned char*)(rsc + 64);

    __shared__ int s_bytemode;

    const int tid = threadIdx.x;
    const int tx = tid & 15, ty = tid >> 4;
    const int bh = blockIdx.y;
    const int b = bh >> 3, h = bh & 7;
    const int i0 = blockIdx.x * 64;

    if (tid == 0) s_bytemode = 0;
    __syncthreads();
    {
        unsigned w = ((const unsigned*)mask)[tid];
        if (w != 0u && w != 1u && w != 0x3F800000u) atomicOr(&s_bytemode, 1);
    }

    {
        const float* qp = Q + ((size_t)bh * T_ + i0) * D_;
        const float* up = pbu + h * D_;
#pragma unroll
        for (int s = 0; s < 4; s++) {
            int f = tid + 256 * s;
            int r = f >> 4, c4 = (f & 15) * 4;
            float4 v4 = *(const float4*)(qp + r * D_ + c4);
            quT[(c4 + 0) * 68 + r] = v4.x + up[c4 + 0];
            quT[(c4 + 1) * 68 + r] = v4.y + up[c4 + 1];
            quT[(c4 + 2) * 68 + r] = v4.z + up[c4 + 2];
            quT[(c4 + 3) * 68 + r] = v4.w + up[c4 + 3];
        }
    }
    if (tid < 64) {
        duv[tid]  = pbv[h * D_ + tid] - pbu[h * D_ + tid];
        mrun[tid] = -1e30f;
        lrun[tid] = 0.f;
    }

    float o[4][4];
#pragma unroll
    for (int i = 0; i < 4; i++)
#pragma unroll
        for (int j = 0; j < 4; j++) o[i][j] = 0.f;

    const float* Ph = P + (size_t)h * PL_ * D_;

    for (int jt = -1; jt < 16; jt++) {
        const int j0 = (jt < 0) ? 0 : jt * 64;
        const int Lb = (jt < 0) ? (960 - i0) : (1024 - i0 + j0);
        const int colbase = (jt < 0) ? 0 : ((64 + j0) & 127);

        if (jt >= 0) {
            const float* kp = K + ((size_t)bh * T_ + j0) * D_;
            const float* vp = V + ((size_t)bh * T_ + j0) * D_;
#pragma unroll
            for (int s = 0; s < 4; s++) {
                int f = tid + 256 * s;
                int r = f >> 4, c4 = (f & 15) * 4;
                float4 kv = *(const float4*)(kp + r * D_ + c4);
                ktT[(c4 + 0) * 68 + r] = kv.x;
                ktT[(c4 + 1) * 68 + r] = kv.y;
                ktT[(c4 + 2) * 68 + r] = kv.z;
                ktT[(c4 + 3) * 68 + r] = kv.w;
                float4 vv = *(const float4*)(vp + r * D_ + c4);
                *(float4*)(vt + r * 68 + c4) = vv;
            }
            {
                int r = tid >> 2; int off = (tid & 3) * 16;
                size_t elem = (size_t)(b * T_ + i0 + r) * T_ + j0 + off;
                if (s_bytemode) {
                    *(uint4*)(mt + r * 64 + off) = *(const uint4*)(mask + elem);
                } else {
                    const uint4* mp = (const uint4*)((const unsigned*)mask + elem);
#pragma unroll
                    for (int q4 = 0; q4 < 4; q4++) {
                        uint4 m4 = mp[q4];
                        mt[r * 64 + off + q4 * 4 + 0] = (m4.x != 0u);
                        mt[r * 64 + off + q4 * 4 + 1] = (m4.y != 0u);
                        mt[r * 64 + off + q4 * 4 + 2] = (m4.z != 0u);
                        mt[r * 64 + off + q4 * 4 + 3] = (m4.w != 0u);
                    }
                }
            }
        }
#pragma unroll
        for (int s = 0; s < 4; s++) {
            int f = tid + 256 * s;
            int r = f >> 4, c4 = (f & 15) * 4;
            int l = Lb + r;
            float4 pv = make_float4(0.f, 0.f, 0.f, 0.f);
            if (l < PL_) pv = *(const float4*)(Ph + (size_t)l * D_ + c4);
            sT[(c4 + 0) * 68 + r] = pv.x;
            sT[(c4 + 1) * 68 + r] = pv.y;
            sT[(c4 + 2) * 68 + r] = pv.z;
            sT[(c4 + 3) * 68 + r] = pv.w;
        }
        __syncthreads();

        if (tid < 64) {
            float acc = 0.f;
#pragma unroll 16
            for (int d = 0; d < 64; d++) acc += duv[d] * sT[d * 68 + tid];
            wp[tid] = acc;
        }
        __syncthreads();

        {
            float acc[4][4];
#pragma unroll
            for (int i = 0; i < 4; i++)
#pragma unroll
                for (int j = 0; j < 4; j++) acc[i][j] = 0.f;
#pragma unroll 8
            for (int d = 0; d < 64; d++) {
                float4 av = *(const float4*)&quT[d * 68 + ty * 4];
                float4 pv = *(const float4*)&sT[d * 68 + tx * 4];
                float a_[4] = {av.x, av.y, av.z, av.w};
                float p_[4] = {pv.x, pv.y, pv.z, pv.w};
#pragma unroll
                for (int i = 0; i < 4; i++)
#pragma unroll
                    for (int j = 0; j < 4; j++) acc[i][j] += a_[i] * p_[j];
            }
#pragma unroll
            for (int i = 0; i < 4; i++)
#pragma unroll
                for (int j = 0; j < 4; j++)
                    bd[(ty * 4 + i) * 128 + colbase + tx * 4 + j] =
                        acc[i][j] + wp[tx * 4 + j];
        }
        __syncthreads();
        if (jt < 0) continue;

        {
            float acc[4][4];
#pragma unroll
            for (int i = 0; i < 4; i++)
#pragma unroll
                for (int j = 0; j < 4; j++) acc[i][j] = 0.f;
#pragma unroll 8
            for (int d = 0; d < 64; d++) {
                float4 av = *(const float4*)&quT[d * 68 + ty * 4];
                float4 kv = *(const float4*)&ktT[d * 68 + tx * 4];
                float a_[4] = {av.x, av.y, av.z, av.w};
                float k_[4] = {kv.x, kv.y, kv.z, kv.w};
#pragma unroll
                for (int i = 0; i < 4; i++)
#pragma unroll
                    for (int j = 0; j < 4; j++) acc[i][j] += a_[i] * k_[j];
            }
#pragma unroll
            for (int i = 0; i < 4; i++) {
                int ri = ty * 4 + i;
#pragma unroll
                for (int j = 0; j < 4; j++) {
                    int cj = tx * 4 + j;
                    float bdv = bd[ri * 128 + ((63 - ri + j0 + cj) & 127)];
                    float sc = (acc[i][j] + bdv) * 0.125f;
                    if (mt[ri * 64 + cj]) sc = -10000.f;
                    sT[cj * 68 + ri] = sc;
                }
            }
        }
        __syncthreads();

        {
            int r = tid >> 2, sg = tid & 3;
            float mloc = -1e30f;
#pragma unroll 16
            for (int c = 0; c < 16; c++)
                mloc = fmaxf(mloc, sT[(sg * 16 + c) * 68 + r]);
            mloc = fmaxf(mloc, __shfl_xor_sync(0xffffffffu, mloc, 1));
            mloc = fmaxf(mloc, __shfl_xor_sync(0xffffffffu, mloc, 2));
            float mold = mrun[r];
            float mnew = fmaxf(mold, mloc);
            float scale = __expf(mold - mnew);
            float ls = 0.f;
#pragma unroll 16
            for (int c = 0; c < 16; c++) {
                int cc = sg * 16 + c;
                float p = __expf(sT[cc * 68 + r] - mnew);
                ls += p;
                sT[cc * 68 + r] = mt[r * 64 + cc] ? 0.f : p;
            }
            ls += __shfl_xor_sync(0xffffffffu, ls, 1);
            ls += __shfl_xor_sync(0xffffffffu, ls, 2);
            if (sg == 0) {
                mrun[r] = mnew;
                lrun[r] = lrun[r] * scale + ls;
                rsc[r]  = scale;
            }
        }
        __syncthreads();

        {
            float s_[4];
#pragma unroll
            for (int i = 0; i < 4; i++) s_[i] = rsc[ty * 4 + i];
#pragma unroll
            for (int i = 0; i < 4; i++)
#pragma unroll
                for (int j = 0; j < 4; j++) o[i][j] *= s_[i];
#pragma unroll 8
            for (int jj = 0; jj < 64; jj++) {
                float4 av = *(const float4*)&sT[jj * 68 + ty * 4];
                float4 vv = *(const float4*)&vt[jj * 68 + tx * 4];
                float a_[4] = {av.x, av.y, av.z, av.w};
                float v_[4] = {vv.x, vv.y, vv.z, vv.w};
#pragma unroll
                for (int i = 0; i < 4; i++)
#pragma unroll
                    for (int j = 0; j < 4; j++) o[i][j] += a_[i] * v_[j];
            }
        }
        __syncthreads();
    }

    {
        float* xp = g_X + (size_t)(b * T_ + i0) * NF_ + h * D_;
#pragma unroll
        for (int i = 0; i < 4; i++) {
            int r = ty * 4 + i;
            float inv = 1.f / lrun[r];
            float4 v4 = make_float4(o[i][0] * inv, o[i][1] * inv,
                                    o[i][2] * inv, o[i][3] * inv);
            *(float4*)(xp + (size_t)r * NF_ + tx * 4) = v4;
        }
    }
    (void)X;
}

// ======================================================================
extern "C" void kernel_launch(void* const* d_in, const int* in_sizes, int n_in,
                              void* d_out, int out_size)
{
    const float* query   = (const float*)d_in[0];
    const float* key     = (const float*)d_in[1];
    const float* value   = (const float*)d_in[2];
    const unsigned char* mask = (const unsigned char*)d_in[3];
    const float* pos_emb = (const float*)d_in[4];
    const float* Wq  = (const float*)d_in[5];
    const float* bq  = (const float*)d_in[6];
    const float* Wk  = (const float*)d_in[7];
    const float* bk  = (const float*)d_in[8];
    const float* Wv  = (const float*)d_in[9];
    const float* bv  = (const float*)d_in[10];
    const float* Wpos= (const float*)d_in[11];
    const float* Wo  = (const float*)d_in[12];
    const float* bo  = (const float*)d_in[13];
    const float* pbu = (const float*)d_in[14];
    const float* pbv = (const float*)d_in[15];

    float *Qd, *Kd, *Vd, *Pd, *Xd;
    cudaGetSymbolAddress((void**)&Qd, g_Q);
    cudaGetSymbolAddress((void**)&Kd, g_K);
    cudaGetSymbolAddress((void**)&Vd, g_V);
    cudaGetSymbolAddress((void**)&Pd, g_P);
    cudaGetSymbolAddress((void**)&Xd, g_X);

    const int GSMEM = 2 * BUFB; // 81920 B
    cudaFuncSetAttribute(sgemm_mma,
                         cudaFuncAttributeMaxDynamicSharedMemorySize, GSMEM);
    const int SMEM = (4 * 64 * 68 + 64 * 128 + 5 * 64) * 4 + 64 * 64; // 107776 B
    cudaFuncSetAttribute(attn_kernel,
                         cudaFuncAttributeMaxDynamicSharedMemorySize, SMEM);

    // projections (tensor-core bf16x2 split via mma.sync)
    sgemm_mma<<<dim3(4, 64), 256, GSMEM>>>(query,  Wq,  bq,  Qd, B_ * T_, 1);
    sgemm_mma<<<dim3(4, 64), 256, GSMEM>>>(key,    Wk,  bk,  Kd, B_ * T_, 1);
    sgemm_mma<<<dim3(4, 64), 256, GSMEM>>>(value,  Wv,  bv,  Vd, B_ * T_, 1);
    sgemm_mma<<<dim3(4, 16), 256, GSMEM>>>(pos_emb, Wpos, nullptr, Pd, PL_, 2);

    // fused attention (fp32)
    attn_kernel<<<dim3(T_ / 64, B_ * H_), 256, SMEM>>>(
        Qd, Kd, Vd, Pd, mask, pbu, pbv, Xd);

    // output projection
    sgemm_mma<<<dim3(4, 64), 256, GSMEM>>>(Xd, Wo, bo, (float*)d_out, B_ * T_, 0);
}

// round 8
// speedup vs baseline: 2.3141x; 1.7766x over previous
#include <cuda_runtime.h>
#include <cuda_bf16.h>

#define B_  8
#define T_  1024
#define H_  8
#define D_  64
#define NF_ 512
#define PL_ 2047

// -------- scratch (static device globals; no allocation) --------
__device__ float g_Q[B_*H_*T_*D_];
__device__ float g_P[H_*PL_*D_];
__device__ float g_X[B_*T_*NF_];
__device__ float g_wp[H_*PL_];
__device__ __nv_bfloat16 g_Kh[B_*H_*T_*D_], g_Kl[B_*H_*T_*D_];
__device__ __nv_bfloat16 g_Vh[B_*H_*T_*D_], g_Vl[B_*H_*T_*D_];
__device__ __nv_bfloat16 g_Ph[H_*PL_*D_],  g_Pl[H_*PL_*D_];

// ===================== mma.sync helpers (base ISA) =====================
__device__ __forceinline__ unsigned smem_u32(const void* p) {
    unsigned a;
    asm("{ .reg .u64 t; cvta.to.shared.u64 t, %1; cvt.u32.u64 %0, t; }"
        : "=r"(a) : "l"(p));
    return a;
}
__device__ __forceinline__ void ldsm_x4(unsigned* r, unsigned addr) {
    asm volatile("ldmatrix.sync.aligned.m8n8.x4.shared.b16 {%0,%1,%2,%3}, [%4];"
                 : "=r"(r[0]), "=r"(r[1]), "=r"(r[2]), "=r"(r[3]) : "r"(addr));
}
__device__ __forceinline__ void ldsm_x2(unsigned* r, unsigned addr) {
    asm volatile("ldmatrix.sync.aligned.m8n8.x2.shared.b16 {%0,%1}, [%2];"
                 : "=r"(r[0]), "=r"(r[1]) : "r"(addr));
}
__device__ __forceinline__ void ldsm_x4t(unsigned* r, unsigned addr) {
    asm volatile("ldmatrix.sync.aligned.m8n8.x4.trans.shared.b16 {%0,%1,%2,%3}, [%4];"
                 : "=r"(r[0]), "=r"(r[1]), "=r"(r[2]), "=r"(r[3]) : "r"(addr));
}
__device__ __forceinline__ void mma_bf16(float* c, const unsigned* a, const unsigned* b) {
    asm volatile(
        "mma.sync.aligned.m16n8k16.row.col.f32.bf16.bf16.f32 "
        "{%0,%1,%2,%3}, {%4,%5,%6,%7}, {%8,%9}, {%0,%1,%2,%3};"
        : "+f"(c[0]), "+f"(c[1]), "+f"(c[2]), "+f"(c[3])
        : "r"(a[0]), "r"(a[1]), "r"(a[2]), "r"(a[3]), "r"(b[0]), "r"(b[1]));
}
__device__ __forceinline__ void split_bf16(float4 v, uint2& h, uint2& l) {
    __nv_bfloat16 h0 = __float2bfloat16(v.x), h1 = __float2bfloat16(v.y);
    __nv_bfloat16 h2 = __float2bfloat16(v.z), h3 = __float2bfloat16(v.w);
    __nv_bfloat16 l0 = __float2bfloat16(v.x - __bfloat162float(h0));
    __nv_bfloat16 l1 = __float2bfloat16(v.y - __bfloat162float(h1));
    __nv_bfloat16 l2 = __float2bfloat16(v.z - __bfloat162float(h2));
    __nv_bfloat16 l3 = __float2bfloat16(v.w - __bfloat162float(h3));
    h.x = (unsigned)__bfloat16_as_ushort(h0) | ((unsigned)__bfloat16_as_ushort(h1) << 16);
    h.y = (unsigned)__bfloat16_as_ushort(h2) | ((unsigned)__bfloat16_as_ushort(h3) << 16);
    l.x = (unsigned)__bfloat16_as_ushort(l0) | ((unsigned)__bfloat16_as_ushort(l1) << 16);
    l.y = (unsigned)__bfloat16_as_ushort(l2) | ((unsigned)__bfloat16_as_ushort(l3) << 16);
}
__device__ __forceinline__ void splitpack(float a, float b, unsigned& hi, unsigned& lo) {
    __nv_bfloat16 ha = __float2bfloat16(a), hb = __float2bfloat16(b);
    __nv_bfloat16 la = __float2bfloat16(a - __bfloat162float(ha));
    __nv_bfloat16 lb = __float2bfloat16(b - __bfloat162float(hb));
    hi = (unsigned)__bfloat16_as_ushort(ha) | ((unsigned)__bfloat16_as_ushort(hb) << 16);
    lo = (unsigned)__bfloat16_as_ushort(la) | ((unsigned)__bfloat16_as_ushort(lb) << 16);
}

// ======================================================================
// bf16x2-split tensor-core SGEMM-NT (passing round-7 core, extended):
// mode 0: fp32 row-major. mode 1: fp32 [B,H,T,D]. mode 3: bf16 h/l [B,H,T,D].
// mode 4: fp32 [H,PL,D] + bf16 h/l same layout.
// ======================================================================
#define LDA 40
#define MATB (128 * LDA * 2)
#define BUFB (4 * MATB)

__global__ void __launch_bounds__(256) sgemm_mma(
    const float* __restrict__ A, const float* __restrict__ W,
    const float* __restrict__ bias, float* __restrict__ C,
    __nv_bfloat16* __restrict__ Ch, __nv_bfloat16* __restrict__ Cl,
    int M, int mode)
{
    extern __shared__ __align__(16) unsigned char smem[];
    const unsigned sbase = smem_u32(smem);
    const int tid = threadIdx.x;
    const int lane = tid & 31, wid = tid >> 5;
    const int wm = wid & 3, wn = wid >> 2;
    const int m0 = blockIdx.y * 128;
    const int n0 = blockIdx.x * 128;

    float acc[2][8][4];
#pragma unroll
    for (int mi = 0; mi < 2; mi++)
#pragma unroll
        for (int ni = 0; ni < 8; ni++)
#pragma unroll
            for (int q = 0; q < 4; q++) acc[mi][ni][q] = 0.f;

    const int lrow = tid >> 3;
    const int lcol = (tid & 7) * 4;

    {
#pragma unroll
        for (int i = 0; i < 4; i++) {
            int r = lrow + 32 * i;
            float4 a4 = make_float4(0.f, 0.f, 0.f, 0.f);
            if (m0 + r < M) a4 = *(const float4*)(A + (size_t)(m0 + r) * 512 + lcol);
            float4 b4 = *(const float4*)(W + (size_t)(n0 + r) * 512 + lcol);
            uint2 h, l;
            split_bf16(a4, h, l);
            *(uint2*)(smem + (size_t)r * LDA * 2 + lcol * 2) = h;
            *(uint2*)(smem + MATB + (size_t)r * LDA * 2 + lcol * 2) = l;
            split_bf16(b4, h, l);
            *(uint2*)(smem + 2 * MATB + (size_t)r * LDA * 2 + lcol * 2) = h;
            *(uint2*)(smem + 3 * MATB + (size_t)r * LDA * 2 + lcol * 2) = l;
        }
    }
    __syncthreads();

    const unsigned aoff = ((unsigned)(wm * 32 + (lane & 15)) * LDA + (lane >> 4) * 8) * 2;
    const unsigned boff = ((unsigned)(wn * 64 + (lane & 7)) * LDA + ((lane >> 3) & 1) * 8) * 2;

    for (int c = 0; c < 16; c++) {
        const unsigned buf = sbase + (unsigned)(c & 1) * BUFB;
        const int nb = (c + 1) & 1;

        float4 pa[4], pb[4];
        if (c < 15) {
            const int k0 = (c + 1) * 32;
#pragma unroll
            for (int i = 0; i < 4; i++) {
                int r = lrow + 32 * i;
                pa[i] = make_float4(0.f, 0.f, 0.f, 0.f);
                if (m0 + r < M)
                    pa[i] = *(const float4*)(A + (size_t)(m0 + r) * 512 + k0 + lcol);
                pb[i] = *(const float4*)(W + (size_t)(n0 + r) * 512 + k0 + lcol);
            }
        }

#pragma unroll
        for (int ks = 0; ks < 2; ks++) {
            const unsigned kb = (unsigned)(ks * 16) * 2;
            unsigned ah[2][4], al[2][4], bh[8][2], bl[8][2];
#pragma unroll
            for (int mi = 0; mi < 2; mi++) {
                ldsm_x4(ah[mi], buf + aoff + (unsigned)mi * (16 * LDA * 2) + kb);
                ldsm_x4(al[mi], buf + MATB + aoff + (unsigned)mi * (16 * LDA * 2) + kb);
            }
#pragma unroll
            for (int ni = 0; ni < 8; ni++) {
                ldsm_x2(bh[ni], buf + 2 * MATB + boff + (unsigned)ni * (8 * LDA * 2) + kb);
                ldsm_x2(bl[ni], buf + 3 * MATB + boff + (unsigned)ni * (8 * LDA * 2) + kb);
            }
#pragma unroll
            for (int mi = 0; mi < 2; mi++)
#pragma unroll
                for (int ni = 0; ni < 8; ni++) mma_bf16(acc[mi][ni], ah[mi], bh[ni]);
#pragma unroll
            for (int mi = 0; mi < 2; mi++)
#pragma unroll
                for (int ni = 0; ni < 8; ni++) mma_bf16(acc[mi][ni], ah[mi], bl[ni]);
#pragma unroll
            for (int mi = 0; mi < 2; mi++)
#pragma unroll
                for (int ni = 0; ni < 8; ni++) mma_bf16(acc[mi][ni], al[mi], bh[ni]);
        }

        if (c < 15) {
            unsigned char* dst = smem + (size_t)nb * BUFB;
#pragma unroll
            for (int i = 0; i < 4; i++) {
                int r = lrow + 32 * i;
                uint2 h, l;
                split_bf16(pa[i], h, l);
                *(uint2*)(dst + (size_t)r * LDA * 2 + lcol * 2) = h;
                *(uint2*)(dst + MATB + (size_t)r * LDA * 2 + lcol * 2) = l;
                split_bf16(pb[i], h, l);
                *(uint2*)(dst + 2 * MATB + (size_t)r * LDA * 2 + lcol * 2) = h;
                *(uint2*)(dst + 3 * MATB + (size_t)r * LDA * 2 + lcol * 2) = l;
            }
        }
        __syncthreads();
    }

    {
        const int tq = lane >> 2, tr = (lane & 3) * 2;
#pragma unroll
        for (int mi = 0; mi < 2; mi++) {
#pragma unroll
            for (int ni = 0; ni < 8; ni++) {
                const int gcol = n0 + wn * 64 + ni * 8 + tr;
                float bx = 0.f, by = 0.f;
                if (bias) { bx = bias[gcol]; by = bias[gcol + 1]; }
#pragma unroll
                for (int hf = 0; hf < 2; hf++) {
                    const int row = m0 + wm * 32 + mi * 16 + tq + hf * 8;
                    if (row >= M) continue;
                    float2 v;
                    v.x = acc[mi][ni][hf * 2 + 0] + bx;
                    v.y = acc[mi][ni][hf * 2 + 1] + by;
                    if (mode == 0) {
                        *(float2*)(C + (size_t)row * 512 + gcol) = v;
                    } else if (mode == 1) {
                        int bb = row >> 10, t = row & 1023;
                        int hh = gcol >> 6, d0 = gcol & 63;
                        *(float2*)(C + (((size_t)(bb * H_ + hh)) * T_ + t) * D_ + d0) = v;
                    } else if (mode == 3) {
                        int bb = row >> 10, t = row & 1023;
                        int hh = gcol >> 6, d0 = gcol & 63;
                        size_t o = (((size_t)(bb * H_ + hh)) * T_ + t) * D_ + d0;
                        unsigned ph, pl;
                        splitpack(v.x, v.y, ph, pl);
                        *(unsigned*)(Ch + o) = ph;
                        *(unsigned*)(Cl + o) = pl;
                    } else { // mode 4
                        int hh = gcol >> 6, d0 = gcol & 63;
                        size_t o = ((size_t)hh * PL_ + row) * D_ + d0;
                        *(float2*)(C + o) = v;
                        unsigned ph, pl;
                        splitpack(v.x, v.y, ph, pl);
                        *(unsigned*)(Ch + o) = ph;
                        *(unsigned*)(Cl + o) = pl;
                    }
                }
            }
        }
    }
}

// ======================================================================
// wp[h][l] = (pos_bias_v - pos_bias_u) . p[h][l][:]
// ======================================================================
__global__ void wp_kernel(const float* __restrict__ P,
                          const float* __restrict__ pbu, const float* __restrict__ pbv,
                          float* __restrict__ wp)
{
    int idx = blockIdx.x * 256 + threadIdx.x;
    if (idx >= H_ * PL_) return;
    int h = idx / PL_, l = idx - h * PL_;
    const float* pp = P + ((size_t)h * PL_ + l) * D_;
    const float* u = pbu + h * D_;
    const float* v = pbv + h * D_;
    float acc = 0.f;
#pragma unroll 16
    for (int d = 0; d < D_; d++) acc += (v[d] - u[d]) * pp[d];
    wp[idx] = acc;
}

// ======================================================================
// Tensor-core fused rel-pos flash attention.
// grid (16, 64), 256 threads, 8 warps = 4m x 2n over a 64x64 tile.
// QK/BD/AV all 3-pass bf16-split mma.sync. BD ring + gather identical
// in formula to the verified fp32 version.
// ======================================================================
#define KPB 144
#define SQH 0
#define SQL 9216
#define SKH 18432
#define SKL 27648
#define SVH 36864
#define SVL 46080
#define SPWH 55296
#define SPWL 64512
#define SRING 73728
#define SMASK 106496
#define SMRUN 110592
#define SLRUN 110848
#define SRSC  111104
#define SWPW  111360
#define SHMAX 111616
#define SHSUM 112128
#define ATSMEM 112640

__global__ void __launch_bounds__(256) attn_tc(
    const float* __restrict__ Qg,
    const __nv_bfloat16* __restrict__ Khg, const __nv_bfloat16* __restrict__ Klg,
    const __nv_bfloat16* __restrict__ Vhg, const __nv_bfloat16* __restrict__ Vlg,
    const __nv_bfloat16* __restrict__ Phg, const __nv_bfloat16* __restrict__ Plg,
    const float* __restrict__ wpg, const unsigned char* __restrict__ mask,
    const float* __restrict__ pbu, float* __restrict__ Xg)
{
    extern __shared__ __align__(16) unsigned char sm[];
    const unsigned sb = smem_u32(sm);
    float* ring = (float*)(sm + SRING);
    unsigned char* mt = sm + SMASK;
    float* mrun = (float*)(sm + SMRUN);
    float* lrun = (float*)(sm + SLRUN);
    float* rsc  = (float*)(sm + SRSC);
    float* wpw  = (float*)(sm + SWPW);
    float* hmax = (float*)(sm + SHMAX);
    float* hsum = (float*)(sm + SHSUM);
    __shared__ int s_bytemode;

    const int tid = threadIdx.x;
    const int lane = tid & 31, wid = tid >> 5;
    const int wm = wid & 3, wn = wid >> 2;
    const int tq = lane >> 2, c2 = (lane & 3) * 2;
    const int bh = blockIdx.y, b = bh >> 3, h = bh & 7;
    const int i0 = blockIdx.x * 64;
    const int ri0 = wm * 16 + tq, ri1 = ri0 + 8;

    if (tid == 0) s_bytemode = 0;
    __syncthreads();
    {
        unsigned w = ((const unsigned*)mask)[tid];
        if (w != 0u && w != 1u && w != 0x3F800000u) atomicOr(&s_bytemode, 1);
    }

    // Q tile + u bias, split -> smem
    {
        const float* qp = Qg + ((size_t)bh * T_ + i0) * D_;
#pragma unroll
        for (int s = 0; s < 4; s++) {
            int f = tid + 256 * s;
            int r = f >> 4, c4 = (f & 15) * 4;
            float4 v = *(const float4*)(qp + r * D_ + c4);
            float4 u = *(const float4*)(pbu + h * D_ + c4);
            v.x += u.x; v.y += u.y; v.z += u.z; v.w += u.w;
            uint2 hh, ll;
            split_bf16(v, hh, ll);
            *(uint2*)(sm + SQH + r * KPB + c4 * 2) = hh;
            *(uint2*)(sm + SQL + r * KPB + c4 * 2) = ll;
        }
    }
    if (tid < 64) { mrun[tid] = -1e30f; lrun[tid] = 0.f; }

    float O[8][4];
#pragma unroll
    for (int nd = 0; nd < 8; nd++)
#pragma unroll
        for (int q = 0; q < 4; q++) O[nd][q] = 0.f;

    for (int jt = -1; jt < 16; jt++) {
        const int j0 = (jt < 0) ? 0 : jt * 64;
        const int Lb = (jt < 0) ? (960 - i0) : (1024 - i0 + j0);
        const int cbase = (jt < 0) ? 0 : ((64 + j0) & 127);

        // ---- loads ----
        if (jt >= 0) {
#pragma unroll
            for (int s = 0; s < 2; s++) {
                int g = tid + 256 * s;
                int r = g >> 3, ch = g & 7;
                size_t go = ((size_t)bh * T_ + j0 + r) * D_ + ch * 8;
                unsigned so = r * KPB + ch * 16;
                *(uint4*)(sm + SKH + so) = *(const uint4*)(Khg + go);
                *(uint4*)(sm + SKL + so) = *(const uint4*)(Klg + go);
                *(uint4*)(sm + SVH + so) = *(const uint4*)(Vhg + go);
                *(uint4*)(sm + SVL + so) = *(const uint4*)(Vlg + go);
            }
            {
                int r = tid >> 2; int off = (tid & 3) * 16;
                size_t elem = (size_t)(b * T_ + i0 + r) * T_ + j0 + off;
                if (s_bytemode) {
                    *(uint4*)(mt + r * 64 + off) = *(const uint4*)(mask + elem);
                } else {
                    const uint4* mp = (const uint4*)((const unsigned*)mask + elem);
#pragma unroll
                    for (int q4 = 0; q4 < 4; q4++) {
                        uint4 m4 = mp[q4];
                        mt[r * 64 + off + q4 * 4 + 0] = (m4.x != 0u);
                        mt[r * 64 + off + q4 * 4 + 1] = (m4.y != 0u);
                        mt[r * 64 + off + q4 * 4 + 2] = (m4.z != 0u);
                        mt[r * 64 + off + q4 * 4 + 3] = (m4.w != 0u);
                    }
                }
            }
        }
#pragma unroll
        for (int s = 0; s < 2; s++) {
            int g = tid + 256 * s;
            int r = g >> 3, ch = g & 7;
            int l = Lb + r;
            unsigned so = r * KPB + ch * 16;
            uint4 ph = make_uint4(0, 0, 0, 0), pl = make_uint4(0, 0, 0, 0);
            if (l < PL_) {
                size_t go = ((size_t)h * PL_ + l) * D_ + ch * 8;
                ph = *(const uint4*)(Phg + go);
                pl = *(const uint4*)(Plg + go);
            }
            *(uint4*)(sm + SPWH + so) = ph;
            *(uint4*)(sm + SPWL + so) = pl;
        }
        if (tid < 64) wpw[tid] = (Lb + tid < PL_) ? wpg[h * PL_ + Lb + tid] : 0.f;
        __syncthreads();

        // ---- BD mma: Q(rows wm*16) x Pw(cols wn*32) ----
        {
            float cbd[4][4];
#pragma unroll
            for (int ns = 0; ns < 4; ns++)
#pragma unroll
                for (int q = 0; q < 4; q++) cbd[ns][q] = 0.f;
#pragma unroll
            for (int ks = 0; ks < 4; ks++) {
                unsigned ah4[4], al4[4];
                unsigned arow = wm * 16 + (lane & 15);
                unsigned acol = ks * 32 + (lane >> 4) * 16;
                ldsm_x4(ah4, sb + SQH + arow * KPB + acol);
                ldsm_x4(al4, sb + SQL + arow * KPB + acol);
#pragma unroll
                for (int ng = 0; ng < 2; ng++) {
                    unsigned brow = wn * 32 + ng * 16 + (lane & 7) + ((lane >> 4) & 1) * 8;
                    unsigned bcol = ks * 32 + ((lane >> 3) & 1) * 16;
                    unsigned bh4[4], bl4[4];
                    ldsm_x4(bh4, sb + SPWH + brow * KPB + bcol);
                    ldsm_x4(bl4, sb + SPWL + brow * KPB + bcol);
                    mma_bf16(cbd[ng * 2],     ah4, bh4 + 0);
                    mma_bf16(cbd[ng * 2 + 1], ah4, bh4 + 2);
                    mma_bf16(cbd[ng * 2],     ah4, bl4 + 0);
                    mma_bf16(cbd[ng * 2 + 1], ah4, bl4 + 2);
                    mma_bf16(cbd[ng * 2],     al4, bh4 + 0);
                    mma_bf16(cbd[ng * 2 + 1], al4, bh4 + 2);
                }
            }
#pragma unroll
            for (int ns = 0; ns < 4; ns++) {
                int cl = wn * 32 + ns * 8 + c2;
                float w0 = wpw[cl], w1 = wpw[cl + 1];
                ring[ri0 * 128 + ((cbase + cl) & 127)]     = cbd[ns][0] + w0;
                ring[ri0 * 128 + ((cbase + cl + 1) & 127)] = cbd[ns][1] + w1;
                ring[ri1 * 128 + ((cbase + cl) & 127)]     = cbd[ns][2] + w0;
                ring[ri1 * 128 + ((cbase + cl + 1) & 127)] = cbd[ns][3] + w1;
            }
        }
        __syncthreads();
        if (jt < 0) continue;

        // ---- QK mma + scores ----
        float cs[4][4];
#pragma unroll
        for (int ns = 0; ns < 4; ns++)
#pragma unroll
            for (int q = 0; q < 4; q++) cs[ns][q] = 0.f;
#pragma unroll
        for (int ks = 0; ks < 4; ks++) {
            unsigned ah4[4], al4[4];
            unsigned arow = wm * 16 + (lane & 15);
            unsigned acol = ks * 32 + (lane >> 4) * 16;
            ldsm_x4(ah4, sb + SQH + arow * KPB + acol);
            ldsm_x4(al4, sb + SQL + arow * KPB + acol);
#pragma unroll
            for (int ng = 0; ng < 2; ng++) {
                unsigned brow = wn * 32 + ng * 16 + (lane & 7) + ((lane >> 4) & 1) * 8;
                unsigned bcol = ks * 32 + ((lane >> 3) & 1) * 16;
                unsigned bh4[4], bl4[4];
                ldsm_x4(bh4, sb + SKH + brow * KPB + bcol);
                ldsm_x4(bl4, sb + SKL + brow * KPB + bcol);
                mma_bf16(cs[ng * 2],     ah4, bh4 + 0);
                mma_bf16(cs[ng * 2 + 1], ah4, bh4 + 2);
                mma_bf16(cs[ng * 2],     ah4, bl4 + 0);
                mma_bf16(cs[ng * 2 + 1], ah4, bl4 + 2);
                mma_bf16(cs[ng * 2],     al4, bh4 + 0);
                mma_bf16(cs[ng * 2 + 1], al4, bh4 + 2);
            }
        }
#pragma unroll
        for (int ns = 0; ns < 4; ns++) {
            int cj = wn * 32 + ns * 8 + c2;
            float b00 = ring[ri0 * 128 + ((63 - ri0 + j0 + cj) & 127)];
            float b01 = ring[ri0 * 128 + ((63 - ri0 + j0 + cj + 1) & 127)];
            float b10 = ring[ri1 * 128 + ((63 - ri1 + j0 + cj) & 127)];
            float b11 = ring[ri1 * 128 + ((63 - ri1 + j0 + cj + 1) & 127)];
            cs[ns][0] = (cs[ns][0] + b00) * 0.125f;
            cs[ns][1] = (cs[ns][1] + b01) * 0.125f;
            cs[ns][2] = (cs[ns][2] + b10) * 0.125f;
            cs[ns][3] = (cs[ns][3] + b11) * 0.125f;
            unsigned short m0 = *(const unsigned short*)(mt + ri0 * 64 + cj);
            unsigned short m1 = *(const unsigned short*)(mt + ri1 * 64 + cj);
            if (m0 & 0xFF) cs[ns][0] = -10000.f;
            if (m0 >> 8)   cs[ns][1] = -10000.f;
            if (m1 & 0xFF) cs[ns][2] = -10000.f;
            if (m1 >> 8)   cs[ns][3] = -10000.f;
        }

        // ---- online softmax (register fragments) ----
        float mxl = -1e30f, mxh = -1e30f;
#pragma unroll
        for (int ns = 0; ns < 4; ns++) {
            mxl = fmaxf(mxl, fmaxf(cs[ns][0], cs[ns][1]));
            mxh = fmaxf(mxh, fmaxf(cs[ns][2], cs[ns][3]));
        }
        mxl = fmaxf(mxl, __shfl_xor_sync(0xffffffffu, mxl, 1));
        mxl = fmaxf(mxl, __shfl_xor_sync(0xffffffffu, mxl, 2));
        mxh = fmaxf(mxh, __shfl_xor_sync(0xffffffffu, mxh, 1));
        mxh = fmaxf(mxh, __shfl_xor_sync(0xffffffffu, mxh, 2));
        if ((lane & 3) == 0) { hmax[wn * 64 + ri0] = mxl; hmax[wn * 64 + ri1] = mxh; }
        __syncthreads();
        float ml = fmaxf(mrun[ri0], fmaxf(hmax[ri0], hmax[64 + ri0]));
        float mh = fmaxf(mrun[ri1], fmaxf(hmax[ri1], hmax[64 + ri1]));
        float sl = 0.f, sh = 0.f;
#pragma unroll
        for (int ns = 0; ns < 4; ns++) {
            float p0 = __expf(cs[ns][0] - ml);
            float p1 = __expf(cs[ns][1] - ml);
            float p2 = __expf(cs[ns][2] - mh);
            float p3 = __expf(cs[ns][3] - mh);
            sl += p0 + p1; sh += p2 + p3;
            cs[ns][0] = (cs[ns][0] == -10000.f) ? 0.f : p0;
            cs[ns][1] = (cs[ns][1] == -10000.f) ? 0.f : p1;
            cs[ns][2] = (cs[ns][2] == -10000.f) ? 0.f : p2;
            cs[ns][3] = (cs[ns][3] == -10000.f) ? 0.f : p3;
        }
        sl += __shfl_xor_sync(0xffffffffu, sl, 1);
        sl += __shfl_xor_sync(0xffffffffu, sl, 2);
        sh += __shfl_xor_sync(0xffffffffu, sh, 1);
        sh += __shfl_xor_sync(0xffffffffu, sh, 2);
        if ((lane & 3) == 0) { hsum[wn * 64 + ri0] = sl; hsum[wn * 64 + ri1] = sh; }
        __syncthreads();
        if (wn == 0 && (lane & 3) == 0) {
            float mo = mrun[ri0], sc = __expf(mo - ml);
            lrun[ri0] = lrun[ri0] * sc + hsum[ri0] + hsum[64 + ri0];
            mrun[ri0] = ml; rsc[ri0] = sc;
            mo = mrun[ri1]; sc = __expf(mo - mh);
            lrun[ri1] = lrun[ri1] * sc + hsum[ri1] + hsum[64 + ri1];
            mrun[ri1] = mh; rsc[ri1] = sc;
        }
        __syncthreads();
        {
            float scl = rsc[ri0], sch = rsc[ri1];
#pragma unroll
            for (int nd = 0; nd < 8; nd++) {
                O[nd][0] *= scl; O[nd][1] *= scl;
                O[nd][2] *= sch; O[nd][3] *= sch;
            }
        }

        // ---- pack P fragments (C-layout == A-layout) ----
        unsigned pah[2][4], pal[2][4];
#pragma unroll
        for (int ks = 0; ks < 2; ks++) {
            splitpack(cs[2 * ks][0],     cs[2 * ks][1],     pah[ks][0], pal[ks][0]);
            splitpack(cs[2 * ks][2],     cs[2 * ks][3],     pah[ks][1], pal[ks][1]);
            splitpack(cs[2 * ks + 1][0], cs[2 * ks + 1][1], pah[ks][2], pal[ks][2]);
            splitpack(cs[2 * ks + 1][2], cs[2 * ks + 1][3], pah[ks][3], pal[ks][3]);
        }

        // ---- AV mma: O += P x V (V via ldmatrix trans) ----
#pragma unroll
        for (int ks = 0; ks < 2; ks++) {
            unsigned vrow = wn * 32 + ks * 16 + (lane & 7) + ((lane >> 3) & 1) * 8;
#pragma unroll
            for (int nd = 0; nd < 8; nd += 2) {
                unsigned vcol = (unsigned)nd * 16 + ((lane >> 4) & 1) * 16;
                unsigned bh4[4], bl4[4];
                ldsm_x4t(bh4, sb + SVH + vrow * KPB + vcol);
                ldsm_x4t(bl4, sb + SVL + vrow * KPB + vcol);
                mma_bf16(O[nd],     pah[ks], bh4 + 0);
                mma_bf16(O[nd + 1], pah[ks], bh4 + 2);
                mma_bf16(O[nd],     pah[ks], bl4 + 0);
                mma_bf16(O[nd + 1], pah[ks], bl4 + 2);
                mma_bf16(O[nd],     pal[ks], bh4 + 0);
                mma_bf16(O[nd + 1], pal[ks], bh4 + 2);
            }
        }
        __syncthreads();
    }

    // ---- combine the two n-half partial O's, normalize, write ----
    float* ob = (float*)(sm + SRING);  // reuse ring: 64 x 68 fp32
    if (wn == 1) {
#pragma unroll
        for (int nd = 0; nd < 8; nd++) {
            *(float2*)&ob[ri0 * 68 + nd * 8 + c2] = make_float2(O[nd][0], O[nd][1]);
            *(float2*)&ob[ri1 * 68 + nd * 8 + c2] = make_float2(O[nd][2], O[nd][3]);
        }
    }
    __syncthreads();
    if (wn == 0) {
        float il = 1.f / lrun[ri0], ih = 1.f / lrun[ri1];
        float* x0 = Xg + ((size_t)(b * T_ + i0 + ri0)) * NF_ + h * D_;
        float* x1 = Xg + ((size_t)(b * T_ + i0 + ri1)) * NF_ + h * D_;
#pragma unroll
        for (int nd = 0; nd < 8; nd++) {
            float2 o0 = *(float2*)&ob[ri0 * 68 + nd * 8 + c2];
            float2 o1 = *(float2*)&ob[ri1 * 68 + nd * 8 + c2];
            *(float2*)(x0 + nd * 8 + c2) =
                make_float2((O[nd][0] + o0.x) * il, (O[nd][1] + o0.y) * il);
            *(float2*)(x1 + nd * 8 + c2) =
                make_float2((O[nd][2] + o1.x) * ih, (O[nd][3] + o1.y) * ih);
        }
    }
}

// ======================================================================
extern "C" void kernel_launch(void* const* d_in, const int* in_sizes, int n_in,
                              void* d_out, int out_size)
{
    const float* query   = (const float*)d_in[0];
    const float* key     = (const float*)d_in[1];
    const float* value   = (const float*)d_in[2];
    const unsigned char* mask = (const unsigned char*)d_in[3];
    const float* pos_emb = (const float*)d_in[4];
    const float* Wq  = (const float*)d_in[5];
    const float* bq  = (const float*)d_in[6];
    const float* Wk  = (const float*)d_in[7];
    const float* bk  = (const float*)d_in[8];
    const float* Wv  = (const float*)d_in[9];
    const float* bv  = (const float*)d_in[10];
    const float* Wpos= (const float*)d_in[11];
    const float* Wo  = (const float*)d_in[12];
    const float* bo  = (const float*)d_in[13];
    const float* pbu = (const float*)d_in[14];
    const float* pbv = (const float*)d_in[15];

    float *Qd, *Pd, *Xd, *WPd;
    __nv_bfloat16 *Khd, *Kld, *Vhd, *Vld, *Phd, *Pld;
    cudaGetSymbolAddress((void**)&Qd,  g_Q);
    cudaGetSymbolAddress((void**)&Pd,  g_P);
    cudaGetSymbolAddress((void**)&Xd,  g_X);
    cudaGetSymbolAddress((void**)&WPd, g_wp);
    cudaGetSymbolAddress((void**)&Khd, g_Kh);
    cudaGetSymbolAddress((void**)&Kld, g_Kl);
    cudaGetSymbolAddress((void**)&Vhd, g_Vh);
    cudaGetSymbolAddress((void**)&Vld, g_Vl);
    cudaGetSymbolAddress((void**)&Phd, g_Ph);
    cudaGetSymbolAddress((void**)&Pld, g_Pl);

    const int GSMEM = 2 * BUFB;
    cudaFuncSetAttribute(sgemm_mma,
                         cudaFuncAttributeMaxDynamicSharedMemorySize, GSMEM);
    cudaFuncSetAttribute(attn_tc,
                         cudaFuncAttributeMaxDynamicSharedMemorySize, ATSMEM);

    // projections
    sgemm_mma<<<dim3(4, 64), 256, GSMEM>>>(query, Wq, bq, Qd, nullptr, nullptr,
                                           B_ * T_, 1);
    sgemm_mma<<<dim3(4, 64), 256, GSMEM>>>(key, Wk, bk, nullptr, Khd, Kld,
                                           B_ * T_, 3);
    sgemm_mma<<<dim3(4, 64), 256, GSMEM>>>(value, Wv, bv, nullptr, Vhd, Vld,
                                           B_ * T_, 3);
    sgemm_mma<<<dim3(4, 16), 256, GSMEM>>>(pos_emb, Wpos, nullptr, Pd, Phd, Pld,
                                           PL_, 4);
    wp_kernel<<<(H_ * PL_ + 255) / 256, 256>>>(Pd, pbu, pbv, WPd);

    // fused tensor-core attention
    attn_tc<<<dim3(16, 64), 256, ATSMEM>>>(Qd, Khd, Kld, Vhd, Vld, Phd, Pld,
                                           WPd, mask, pbu, Xd);

    // output projection
    sgemm_mma<<<dim3(4, 64), 256, GSMEM>>>(Xd, Wo, bo, (float*)d_out,
                                           nullptr, nullptr, B_ * T_, 0);
}